// round 4
// baseline (speedup 1.0000x reference)
#include <cuda_runtime.h>

#define AR_P 64
#define AR_T 65536
#define CHUNK_L 8192
#define N_CHUNKS 8   // AR_T / CHUNK_L

__device__ __align__(16) float g_hpad[AR_P + CHUNK_L];   // h with 64 leading zeros
__device__ __align__(16) float g_H[CHUNK_L];             // inclusive prefix sum of h
__device__ float g_phi[N_CHUNKS][AR_P];                  // per-chunk boundary projections
__device__ __align__(16) float g_means[AR_T];

// ---------------------------------------------------------------------------
// Conflict-free 64-tap convolution for 4 consecutive outputs.
// out[r] = sum_{i=0}^{63} src[base0 + r - i] * phi[i], r = 0..3.
// src 16B-aligned, base0 multiple of 4.
// ---------------------------------------------------------------------------
__device__ __forceinline__ void conv4_f4(const float* __restrict__ src, int base0,
                                         const float* __restrict__ phi,
                                         float& a0, float& a1, float& a2, float& a3) {
    const float4 va = *reinterpret_cast<const float4*>(&src[base0]);
    const float4 vb = *reinterpret_cast<const float4*>(&src[base0 - 4]);
    float v0 = vb.x, v1 = vb.y, v2 = vb.z, v3 = vb.w;
    float v4 = va.x, v5 = va.y, v6 = va.z, v7 = va.w;
    a0 = 0.f; a1 = 0.f; a2 = 0.f; a3 = 0.f;
    #pragma unroll
    for (int i4 = 0; i4 < 16; i4++) {
        if (i4 > 0) {
            v4 = v0; v5 = v1; v6 = v2; v7 = v3;
            const float4 nv = *reinterpret_cast<const float4*>(&src[base0 - 4 - 4 * i4]);
            v0 = nv.x; v1 = nv.y; v2 = nv.z; v3 = nv.w;
        }
        const float4 p = *reinterpret_cast<const float4*>(&phi[4 * i4]);
        a0 += v4 * p.x; a1 += v5 * p.x; a2 += v6 * p.x; a3 += v7 * p.x;
        a0 += v3 * p.y; a1 += v4 * p.y; a2 += v5 * p.y; a3 += v6 * p.y;
        a0 += v2 * p.z; a1 += v3 * p.z; a2 += v4 * p.z; a3 += v5 * p.z;
        a0 += v1 * p.w; a1 += v2 * p.w; a2 += v3 * p.w; a3 += v4 * p.w;
    }
}

// ---------------------------------------------------------------------------
// Kernel 1 (single block, 512 thr): impulse response by doubling,
// prefix sum, per-chunk boundary projections.
// ---------------------------------------------------------------------------
__global__ __launch_bounds__(512) void k1_prep(const float* __restrict__ params,
                                               const float* __restrict__ bias) {
    __shared__ __align__(16) float Pp[2 * AR_P];        // params + 64 zeros
    __shared__ __align__(16) float hs[AR_P + CHUNK_L];  // padded impulse response
    __shared__ __align__(16) float phi[AR_P];
    __shared__ float red[16];
    __shared__ float Htail[AR_P];                       // H[8191-j]
    __shared__ float stA[AR_P], stB[AR_P];

    const int tid = threadIdx.x;
    const int lane = tid & 31;
    const int wid = tid >> 5;
    const float bv = bias[0];

    if (tid < 2 * AR_P) Pp[tid] = (tid < AR_P) ? params[tid] : 0.0f;
    if (tid < AR_P) hs[tid] = 0.0f;          // left zero pad h_{-64..-1}
    __syncthreads();

    // bootstrap h_0..h_3 (thread 0, trivial)
    if (tid == 0) {
        const float h0 = 1.0f;
        const float h1 = Pp[0] * h0;
        const float h2 = Pp[0] * h1 + Pp[1] * h0;
        const float h3 = Pp[0] * h2 + Pp[1] * h1 + Pp[2] * h0;
        hs[AR_P + 0] = h0; hs[AR_P + 1] = h1; hs[AR_P + 2] = h2; hs[AR_P + 3] = h3;
    }
    __syncthreads();

    // ---- doubling levels n = 4 .. 4096 ----
    for (int n = 4; n < CHUNK_L; n <<= 1) {
        // phi_i = sum_j Pp[i+j] * h_{n-1-j} : 4 threads per i, shfl reduce
        if (tid < 256) {
            const int i = tid >> 2;
            const int q = tid & 3;
            float acc = 0.0f;
            #pragma unroll
            for (int j = 0; j < 16; j++) {
                const int jj = q * 16 + j;
                acc += Pp[i + jj] * hs[AR_P + n - 1 - jj];
            }
            acc += __shfl_xor_sync(0xffffffffu, acc, 1);
            acc += __shfl_xor_sync(0xffffffffu, acc, 2);
            if (q == 0) phi[i] = acc;
        }
        __syncthreads();
        // outputs h[n .. 2n)
        if (n <= 128) {
            if (tid < n) {
                float s0 = 0.f, s1 = 0.f, s2 = 0.f, s3 = 0.f;
                #pragma unroll
                for (int i = 0; i < AR_P; i += 4) {
                    s0 += hs[AR_P + tid - i - 0] * phi[i + 0];
                    s1 += hs[AR_P + tid - i - 1] * phi[i + 1];
                    s2 += hs[AR_P + tid - i - 2] * phi[i + 2];
                    s3 += hs[AR_P + tid - i - 3] * phi[i + 3];
                }
                hs[AR_P + n + tid] = (s0 + s1) + (s2 + s3);
            }
        } else {
            const int nt = n >> 2;
            for (int t = tid; t < nt; t += 512) {
                float a0, a1, a2, a3;
                conv4_f4(hs, AR_P + 4 * t, phi, a0, a1, a2, a3);
                *reinterpret_cast<float4*>(&hs[AR_P + n + 4 * t]) =
                    make_float4(a0, a1, a2, a3);
            }
        }
        __syncthreads();
    }

    // ---- write padded h to global (float4) ----
    {
        const float4* s4 = reinterpret_cast<const float4*>(hs);
        float4* d4 = reinterpret_cast<float4*>(g_hpad);
        for (int q = tid; q < (AR_P + CHUNK_L) / 4; q += 512) d4[q] = s4[q];
    }

    // ---- inclusive prefix sum of h -> g_H (16 elems/thread, 512 thr) ----
    {
        float v[16];
        const int base = tid * 16;
        float s = 0.0f;
        #pragma unroll
        for (int k = 0; k < 16; k++) { v[k] = hs[AR_P + base + k]; s += v[k]; }
        float ss = s;
        #pragma unroll
        for (int o = 1; o < 32; o <<= 1) {
            const float t2 = __shfl_up_sync(0xffffffffu, ss, o);
            if (lane >= o) ss += t2;
        }
        if (lane == 31) red[wid] = ss;
        __syncthreads();
        if (tid < 16) {
            float ws = red[tid];
            #pragma unroll
            for (int o = 1; o < 16; o <<= 1) {
                const float t2 = __shfl_up_sync(0x0000ffffu, ws, o);
                if (tid >= o) ws += t2;
            }
            red[tid] = ws;
        }
        __syncthreads();
        float run = (ss - s) + ((wid > 0) ? red[wid - 1] : 0.0f);
        #pragma unroll
        for (int k = 0; k < 16; k++) {
            run += v[k];
            const int idx = base + k;
            g_H[idx] = run;
            if (idx >= CHUNK_L - AR_P) Htail[CHUNK_L - 1 - idx] = run;  // H[8191-j]
        }
    }
    __syncthreads();

    // ---- sequential hop over the 8 chunk-boundary states ----
    if (tid < AR_P) stA[tid] = 0.0f;          // state[j] = x_{cL-1-j}
    __syncthreads();
    float* scur = stA;
    float* snew = stB;
    for (int c = 0; c < N_CHUNKS; c++) {
        // phi_i = sum_j Pp[i+j] * state[j] : 4 threads per i
        if (tid < 256) {
            const int i = tid >> 2;
            const int q = tid & 3;
            float acc = 0.0f;
            #pragma unroll
            for (int j = 0; j < 16; j++) {
                const int jj = q * 16 + j;
                acc += Pp[i + jj] * scur[jj];
            }
            acc += __shfl_xor_sync(0xffffffffu, acc, 1);
            acc += __shfl_xor_sync(0xffffffffu, acc, 2);
            if (q == 0) { phi[i] = acc; g_phi[c][i] = acc; }
        }
        __syncthreads();
        if (c < N_CHUNKS - 1) {
            // new state[j] = sum_i h[m-i]*phi[i] + bv*H[m],  m = 8191-j
            if (tid < 256) {
                const int j = tid >> 2;
                const int q = tid & 3;
                const int m = CHUNK_L - 1 - j;
                float acc = 0.0f;
                #pragma unroll
                for (int i = 0; i < 16; i++) {
                    const int ii = q * 16 + i;
                    acc += hs[AR_P + m - ii] * phi[ii];
                }
                acc += __shfl_xor_sync(0xffffffffu, acc, 1);
                acc += __shfl_xor_sync(0xffffffffu, acc, 2);
                if (q == 0) snew[j] = acc + bv * Htail[j];
            }
            __syncthreads();
            float* tmp = scur; scur = snew; snew = tmp;
        }
    }
}

// ---------------------------------------------------------------------------
// Kernel 2: fill all means. grid = 64 blocks x 256 threads,
// 4 consecutive outputs per thread, conflict-free float4 windows.
// ---------------------------------------------------------------------------
__global__ __launch_bounds__(256) void k2_means(const float* __restrict__ bias) {
    const int c = blockIdx.x >> 3;
    const int part = blockIdx.x & 7;
    const int m0base = part * 1024;

    __shared__ __align__(16) float phi[AR_P];
    __shared__ __align__(16) float hw[1088];   // h_{m0base-64 .. m0base+1023}

    const int tid = threadIdx.x;
    if (tid < AR_P) phi[tid] = g_phi[c][tid];
    {
        const float4* g4 = reinterpret_cast<const float4*>(&g_hpad[m0base]);
        float4* s4 = reinterpret_cast<float4*>(hw);
        for (int q = tid; q < 1088 / 4; q += 256) s4[q] = g4[q];
    }
    __syncthreads();

    const float bv = bias[0];
    const int d = tid * 4;
    float a0, a1, a2, a3;
    conv4_f4(hw, 64 + d, phi, a0, a1, a2, a3);

    const int m = m0base + d;
    const float4 Hv = *reinterpret_cast<const float4*>(&g_H[m]);
    float4 r;
    r.x = fmaf(bv, Hv.x, a0);
    r.y = fmaf(bv, Hv.y, a1);
    r.z = fmaf(bv, Hv.z, a2);
    r.w = fmaf(bv, Hv.w, a3);
    *reinterpret_cast<float4*>(&g_means[c * CHUNK_L + m]) = r;
}

// ---------------------------------------------------------------------------
// Kernel 3: out[b,t] = means[t] + 0.3*noise[b,t]  (float4 streaming, .cs hints)
// ---------------------------------------------------------------------------
__global__ __launch_bounds__(256) void k3_out(const float4* __restrict__ noise,
                                              float4* __restrict__ out) {
    const int idx = blockIdx.x * 256 + threadIdx.x;
    const int t4 = idx & (AR_T / 4 - 1);
    const float4 nz = __ldcs(&noise[idx]);                           // stream
    const float4 mn = reinterpret_cast<const float4*>(g_means)[t4];  // L2-resident
    float4 r;
    r.x = fmaf(0.3f, nz.x, mn.x);
    r.y = fmaf(0.3f, nz.y, mn.y);
    r.z = fmaf(0.3f, nz.z, mn.z);
    r.w = fmaf(0.3f, nz.w, mn.w);
    __stcs(&out[idx], r);                                            // evict-first
}

extern "C" void kernel_launch(void* const* d_in, const int* in_sizes, int n_in,
                              void* d_out, int out_size) {
    // identify inputs by element count (params=64, bias=1, noise=256*65536)
    const float* params = nullptr;
    const float* bias   = nullptr;
    const float* noise  = nullptr;
    for (int i = 0; i < n_in; i++) {
        if (in_sizes[i] == AR_P)      params = (const float*)d_in[i];
        else if (in_sizes[i] == 1)    bias   = (const float*)d_in[i];
        else                          noise  = (const float*)d_in[i];
    }

    k1_prep<<<1, 512>>>(params, bias);
    k2_means<<<N_CHUNKS * 8, 256>>>(bias);

    const int total4 = out_size / 4;          // 4,194,304 float4s
    k3_out<<<total4 / 256, 256>>>((const float4*)noise, (float4*)d_out);
}